// round 14
// baseline (speedup 1.0000x reference)
#include <cuda_runtime.h>
#include <cuda_fp16.h>

#define NN   100000
#define NE   1600000
#define ET   (NE + NN)
#define NPAD 100096   // multiple of 64 for guard-free GEMM tiles
#define SCAN_BLKS ((NN + 1023) / 1024)   // 98
#define CNT_BLKS  (NE / 256)             // 6250 exactly
#define TR_BLKS   (NN / 16)              // 6250
#define SC_BLKS   ((ET + 255) / 256)     // 6641
#define L2E 1.4426950408889634f

// ---------------- scratch (device globals; no allocations) ----------------
__device__ int    g_deg[NN];          // invariant: all-zero at kernel_launch entry
__device__ int    g_rowptr[NN + 1];
__device__ int    g_rank[NE];         // per-edge rank within its dst segment
__device__ int    g_srcs[ET];
__device__ int    g_aggv[SCAN_BLKS];
__device__ int    g_prefv[SCAN_BLKS];
__device__ int    g_status[SCAN_BLKS];
__device__ float  g_va[7 * 4];        // per-k dot of W1 col-block with a_src/a_dst (xL2E)
__device__ __half g_W2aT[128 * 128];  // fp16 hi part of W2, transposed [N][K]
__device__ __half g_W2bT[128 * 128];  // fp16 residual part, transposed [N][K]
__device__ __half g_h[NPAD * 128];    // transformed features, fp16
__device__ float  g_es[NN * 2];       // attention src scores, PRE-SCALED by log2(e)
__device__ float  g_ed[NN * 2];       // attention dst scores, PRE-SCALED by log2(e)
__device__ __half g_out1[NPAD * 128]; // layer-1 output (relu'd), fp16

__device__ __forceinline__ float ex2f(float x) {
    float r;
    asm("ex2.approx.f32 %0, %1;" : "=f"(r) : "f"(x));
    return r;
}

// ---------------- kernel 1: edge count+rank + prep (W2 split/transpose, va, flags) ----------------
__global__ void k_count_prep(const int* __restrict__ ei,
                             const float* __restrict__ W1,
                             const float* __restrict__ as1, const float* __restrict__ ad1,
                             const float* __restrict__ W2) {
    int b = blockIdx.x;
    int t = threadIdx.x;
    if (b < CNT_BLKS) {
        int i = b * 256 + t;
        int r = atomicAdd(&g_deg[ei[NE + i]], 1);  // dst = ei[1][i]
        g_rank[i] = r;                             // rank within dst segment
    } else if (b == CNT_BLKS) {
        // W2 -> fp16 hi + fp16 residual, transposed to [N][K]
        for (int idx = t; idx < 128 * 128; idx += 256) {
            int k = idx >> 7, n = idx & 127;
            float w = W2[idx];
            __half a = __float2half_rn(w);
            __half bb = __float2half_rn(w - __half2float(a));
            g_W2aT[n * 128 + k] = a;
            g_W2bT[n * 128 + k] = bb;
        }
    } else {
        // va[k][comp]: comp = {es_h0, es_h1, ed_h0, ed_h1}; pre-scaled by log2(e)
        if (t < 28) {
            int k = t >> 2, comp = t & 3;
            int h = comp & 1;
            const float* vec = (comp < 2) ? as1 : ad1;
            float s = 0.f;
#pragma unroll
            for (int c = 0; c < 64; c++) s += W1[k * 128 + h * 64 + c] * vec[h * 64 + c];
            g_va[k * 4 + comp] = s * L2E;
        }
        if (t >= 32 && t < 32 + SCAN_BLKS) g_status[t - 32] = 0;  // reset lookback flags
    }
}

// ---------------- kernel 2: single-pass scan (decoupled lookback) ----------------
__global__ void k_scanall() {  // SCAN_BLKS blocks x 256 threads; 4 nodes/thread
    __shared__ int sh[256];
    __shared__ int s_prefix;
    int b = blockIdx.x;
    int t = threadIdx.x;
    int base = b * 1024;
    int idx = base + t * 4;
    int v[4];
    int s = 0;
#pragma unroll
    for (int r = 0; r < 4; r++) {
        v[r] = (idx + r < NN) ? (g_deg[idx + r] + 1) : 0;  // +1 self-loop
        if (idx + r < NN) g_deg[idx + r] = 0;              // restore invariant
        s += v[r];
    }
    sh[t] = s;
    __syncthreads();
    for (int off = 1; off < 256; off <<= 1) {
        int tv = (t >= off) ? sh[t - off] : 0;
        __syncthreads();
        sh[t] += tv;
        __syncthreads();
    }
    int total = sh[255];
    if (t == 0) {
        if (b == 0) {
            g_prefv[0] = total;
            __threadfence();
            ((volatile int*)g_status)[0] = 2;
            s_prefix = 0;
        } else {
            g_aggv[b] = total;
            __threadfence();
            ((volatile int*)g_status)[b] = 1;
            int run = 0;
            int i = b - 1;
            while (true) {
                int st;
                do { st = ((volatile int*)g_status)[i]; } while (st == 0);
                __threadfence();
                if (st == 1) { run += ((volatile int*)g_aggv)[i]; i--; }
                else         { run += ((volatile int*)g_prefv)[i]; break; }
            }
            g_prefv[b] = run + total;
            __threadfence();
            ((volatile int*)g_status)[b] = 2;
            s_prefix = run;
        }
    }
    __syncthreads();
    int excl = s_prefix + sh[t] - s;
#pragma unroll
    for (int r = 0; r < 4; r++) {
        if (idx + r < NN) {
            g_rowptr[idx + r] = excl;
            excl += v[r];
            if (idx + r == NN - 1) g_rowptr[NN] = excl;
        }
    }
}

// ---------------- kernel 3: fused scatter (atomic-free) + layer-1 transform ----------------
__global__ void k_scatter_transform(const int* __restrict__ ei,
                                    const float* __restrict__ x,
                                    const float* __restrict__ W1) {
    int b = blockIdx.x;
    int t = threadIdx.x;
    if (b < TR_BLKS) {
        __shared__ float sx[16 * 7];
        int nb = b * 16;
        int ch = t & 127;
        int hf = t >> 7;
        float w1r[7];
#pragma unroll
        for (int k = 0; k < 7; k++) w1r[k] = __ldg(&W1[k * 128 + ch]);
        if (t < 112) sx[t] = x[nb * 7 + t];
        __syncthreads();
#pragma unroll
        for (int i = 0; i < 8; i++) {
            int j = hf * 8 + i;
            float acc = 0.f;
#pragma unroll
            for (int k = 0; k < 7; k++) acc += sx[j * 7 + k] * w1r[k];
            g_h[(size_t)(nb + j) * 128 + ch] = __float2half(acc);
        }
        // es/ed: 64 threads, 4 components x 16 nodes, 7-FMA dots with g_va (pre-scaled)
        if (t < 64) {
            int j = t >> 2, comp = t & 3;
            int n = nb + j;
            float val = 0.f;
#pragma unroll
            for (int k = 0; k < 7; k++) val += sx[j * 7 + k] * g_va[k * 4 + comp];
            if (comp < 2) g_es[2 * n + comp] = val;
            else          g_ed[2 * n + comp - 2] = val;
        }
    } else {
        int i = (b - TR_BLKS) * 256 + t;
        if (i < NE) {
            int s = ei[i], d = ei[NE + i];
            int pos = __ldg(&g_rowptr[d]) + 1 + g_rank[i];  // slot 0 = self-loop
            g_srcs[pos] = s;
        } else if (i < ET) {
            int n = i - NE;
            g_srcs[__ldg(&g_rowptr[n])] = n;
        }
    }
}

// ---------------- segment-softmax + aggregation ----------------
// Warp per node (4 sequential). Lane computes (src, w0, w1) for its edge into
// per-warp smem float4; broadcast loop (LDS.128, unroll x4) accumulates both the
// weighted features AND the weight sum redundantly in every lane. Scores are
// pre-scaled by log2(e) so the per-edge weight is a bare ex2.approx.
// LAYER==2 additionally runs the fused classifier for the block's 32 nodes.
// Occupancy knob: 7 blocks/SM (forces regs <= 36; kernel is latency-bound with
// L1 at 48% and issue at 55%, so more resident warps convert directly to issue).
template <int LAYER>
__global__ void __launch_bounds__(256, 7) k_agg(const float* __restrict__ bias,
                                                const float* __restrict__ Wc1,
                                                const float* __restrict__ bc1,
                                                const float* __restrict__ Wc2,
                                                const float* __restrict__ bc2,
                                                float* __restrict__ out) {
    __shared__ float4 sMeta[8][32];
    __shared__ float  sCls[LAYER == 2 ? (32 * 64 + 64 * 64 + 64 * 4 + 64 + 4) : 1];
    int wip = threadIdx.x >> 5;
    int gw = (blockIdx.x * blockDim.x + threadIdx.x) >> 5;
    int lane = threadIdx.x & 31;
    int head = lane >> 4;
    float4 bv = make_float4(0.f, 0.f, 0.f, 0.f);
    if (LAYER == 1)      bv = *(const float4*)(bias + lane * 4);
    else if (lane < 16)  bv = *(const float4*)(bias + lane * 4);
    const __half* hlane = g_h + lane * 4;   // lane's 4-channel column base

    for (int q = 0; q < 4; q++) {
        int n = gw * 4 + q;
        int beg = g_rowptr[n], end = g_rowptr[n + 1];
        float2 edv = *(const float2*)(g_ed + 2 * n);

        float sw = 0.f;
        float4 acc = make_float4(0.f, 0.f, 0.f, 0.f);

        for (int base = beg; base < end; base += 32) {
            int j = base + lane;
            float4 meta = make_float4(0.f, 0.f, 0.f, 0.f);
            if (j < end) {
                int src = __ldg(&g_srcs[j]);
                float2 es = *(const float2*)(g_es + 2 * src);
                float e0 = es.x + edv.x; e0 = e0 > 0.f ? e0 : 0.2f * e0;
                float e1 = es.y + edv.y; e1 = e1 > 0.f ? e1 : 0.2f * e1;
                meta = make_float4(__int_as_float(src), ex2f(e0), ex2f(e1), 0.f);
            }
            sMeta[wip][lane] = meta;
            __syncwarp();

            int cnt = end - base; if (cnt > 32) cnt = 32;
            int jj = 0;
            for (; jj + 4 <= cnt; jj += 4) {
                float4 mA = sMeta[wip][jj];
                float4 mB = sMeta[wip][jj + 1];
                float4 mC = sMeta[wip][jj + 2];
                float4 mD = sMeta[wip][jj + 3];
                float wA = head ? mA.z : mA.y;
                float wB = head ? mB.z : mB.y;
                float wC = head ? mC.z : mC.y;
                float wD = head ? mD.z : mD.y;
                uint2 uA = *(const uint2*)(hlane + (size_t)__float_as_int(mA.x) * 128);
                uint2 uB = *(const uint2*)(hlane + (size_t)__float_as_int(mB.x) * 128);
                uint2 uC = *(const uint2*)(hlane + (size_t)__float_as_int(mC.x) * 128);
                uint2 uD = *(const uint2*)(hlane + (size_t)__float_as_int(mD.x) * 128);
                sw += (wA + wB) + (wC + wD);
                float2 a01 = __half22float2(*(__half2*)&uA.x);
                float2 a23 = __half22float2(*(__half2*)&uA.y);
                float2 b01 = __half22float2(*(__half2*)&uB.x);
                float2 b23 = __half22float2(*(__half2*)&uB.y);
                float2 c01 = __half22float2(*(__half2*)&uC.x);
                float2 c23 = __half22float2(*(__half2*)&uC.y);
                float2 d01 = __half22float2(*(__half2*)&uD.x);
                float2 d23 = __half22float2(*(__half2*)&uD.y);
                acc.x += wA * a01.x + wB * b01.x + wC * c01.x + wD * d01.x;
                acc.y += wA * a01.y + wB * b01.y + wC * c01.y + wD * d01.y;
                acc.z += wA * a23.x + wB * b23.x + wC * c23.x + wD * d23.x;
                acc.w += wA * a23.y + wB * b23.y + wC * c23.y + wD * d23.y;
            }
            for (; jj < cnt; jj++) {
                float4 mA = sMeta[wip][jj];
                float wA = head ? mA.z : mA.y;
                uint2 uA = *(const uint2*)(hlane + (size_t)__float_as_int(mA.x) * 128);
                sw += wA;
                float2 a01 = __half22float2(*(__half2*)&uA.x);
                float2 a23 = __half22float2(*(__half2*)&uA.y);
                acc.x += wA * a01.x; acc.y += wA * a01.y;
                acc.z += wA * a23.x; acc.w += wA * a23.y;
            }
            __syncwarp();
        }

        float invs = 1.f / sw;

        if (LAYER == 1) {
            float4 o;
            o.x = fmaxf(acc.x * invs + bv.x, 0.f);
            o.y = fmaxf(acc.y * invs + bv.y, 0.f);
            o.z = fmaxf(acc.z * invs + bv.z, 0.f);
            o.w = fmaxf(acc.w * invs + bv.w, 0.f);
            __half2 h01 = __floats2half2_rn(o.x, o.y);
            __half2 h23 = __floats2half2_rn(o.z, o.w);
            uint2 u;
            u.x = *(unsigned*)&h01; u.y = *(unsigned*)&h23;
            ((uint2*)(g_out1 + (size_t)n * 128))[lane] = u;
        } else {
            acc.x *= invs; acc.y *= invs; acc.z *= invs; acc.w *= invs;
            acc.x += __shfl_xor_sync(0xffffffffu, acc.x, 16);
            acc.y += __shfl_xor_sync(0xffffffffu, acc.y, 16);
            acc.z += __shfl_xor_sync(0xffffffffu, acc.z, 16);
            acc.w += __shfl_xor_sync(0xffffffffu, acc.w, 16);
            if (lane < 16) {
                float4 o;
                o.x = 0.5f * acc.x + bv.x;
                o.y = 0.5f * acc.y + bv.y;
                o.z = 0.5f * acc.z + bv.z;
                o.w = 0.5f * acc.w + bv.w;
                // node-mean output to smem for the fused classifier
                *(float4*)&sCls[(wip * 4 + q) * 64 + lane * 4] = o;
            }
        }
    }

    // ---------------- fused classifier (LAYER==2 only) ----------------
    if (LAYER == 2) {
        float* sOut = sCls;                 // [32][64] node features, then hidden
        float* sW1v = sCls + 2048;          // [64][64]
        float* sW2v = sCls + 2048 + 4096;   // [64][4]
        float* sb1v = sCls + 2048 + 4096 + 256;
        float* sb2v = sCls + 2048 + 4096 + 256 + 64;
        int tid = threadIdx.x;
        int nbase = blockIdx.x * 32;

        __syncthreads();
#pragma unroll
        for (int r = 0; r < 4; r++)
            ((float4*)sW1v)[tid + r * 256] = ((const float4*)Wc1)[tid + r * 256];
        if (tid < 64) {
            ((float4*)sW2v)[tid] = ((const float4*)Wc2)[tid];
            sb1v[tid] = bc1[tid];
        }
        if (tid < 4) sb2v[tid] = bc2[tid];
        __syncthreads();

        // hidden = relu(v @ Wc1 + bc1), 32 nodes in 2 passes, compute to regs
        int node = tid >> 4;
        int cq = tid & 15;
        float hreg[2][4];
#pragma unroll
        for (int p = 0; p < 2; p++) {
            int nd = p * 16 + node;
            float a0 = sb1v[cq * 4], a1 = sb1v[cq * 4 + 1];
            float a2 = sb1v[cq * 4 + 2], a3 = sb1v[cq * 4 + 3];
#pragma unroll
            for (int k = 0; k < 64; k++) {
                float v = sOut[nd * 64 + k];
                float4 wv = *(float4*)&sW1v[k * 64 + cq * 4];
                a0 += v * wv.x; a1 += v * wv.y; a2 += v * wv.z; a3 += v * wv.w;
            }
            hreg[p][0] = fmaxf(a0, 0.f); hreg[p][1] = fmaxf(a1, 0.f);
            hreg[p][2] = fmaxf(a2, 0.f); hreg[p][3] = fmaxf(a3, 0.f);
        }
        __syncthreads();
#pragma unroll
        for (int p = 0; p < 2; p++)
            *(float4*)&sOut[(p * 16 + node) * 64 + cq * 4] =
                make_float4(hreg[p][0], hreg[p][1], hreg[p][2], hreg[p][3]);
        __syncthreads();

        // out = hidden @ Wc2 + bc2 (32 nodes x 4 classes)
        if (tid < 128) {
            int n2 = tid >> 2, o = tid & 3;
            float a = sb2v[o];
#pragma unroll
            for (int k = 0; k < 64; k++) a += sOut[n2 * 64 + k] * sW2v[k * 4 + o];
            out[(size_t)(nbase + n2) * 4 + o] = a;
        }
    }
}

// ---------------- layer 2 GEMM on tensor cores + fused attention scores ----------------
__global__ void k_gemm2(const float* __restrict__ as, const float* __restrict__ ad) {
    __shared__ __half sA[64 * 136];
    __shared__ __half sB[128 * 136];
    __shared__ float  sEs[64][2], sEd[64][2];
    int tid = threadIdx.x;             // 256
    int lane = tid & 31;
    int w = tid >> 5;
    int wm = w >> 1;
    int wn = w & 1;
    int nbase = blockIdx.x * 64;

#pragma unroll
    for (int r = 0; r < 4; r++) {
        int idx = tid + r * 256;
        int row = idx >> 4, c8 = idx & 15;
        uint4 u = ((const uint4*)(g_out1 + (size_t)nbase * 128))[idx];
        *(uint4*)&sA[row * 136 + c8 * 8] = u;
    }

    float acc[8][4];
#pragma unroll
    for (int nt = 0; nt < 8; nt++) { acc[nt][0] = acc[nt][1] = acc[nt][2] = acc[nt][3] = 0.f; }

    int r0 = lane >> 2;
    int kq = (lane & 3) * 2;

    const __half* W2p[2] = {g_W2aT, g_W2bT};
#pragma unroll
    for (int part = 0; part < 2; part++) {
        __syncthreads();
#pragma unroll
        for (int r = 0; r < 8; r++) {
            int idx = tid + r * 256;
            int row = idx >> 4, c8 = idx & 15;
            uint4 u = ((const uint4*)W2p[part])[idx];
            *(uint4*)&sB[row * 136 + c8 * 8] = u;
        }
        __syncthreads();
#pragma unroll
        for (int ks = 0; ks < 8; ks++) {
            int k0 = ks * 16 + kq;
            int arow = wm * 16 + r0;
            unsigned a0 = *(const unsigned*)&sA[arow * 136 + k0];
            unsigned a1 = *(const unsigned*)&sA[(arow + 8) * 136 + k0];
            unsigned a2 = *(const unsigned*)&sA[arow * 136 + k0 + 8];
            unsigned a3 = *(const unsigned*)&sA[(arow + 8) * 136 + k0 + 8];
#pragma unroll
            for (int nt = 0; nt < 8; nt++) {
                int col = wn * 64 + nt * 8 + r0;
                unsigned b0 = *(const unsigned*)&sB[col * 136 + k0];
                unsigned b1 = *(const unsigned*)&sB[col * 136 + k0 + 8];
                asm volatile(
                    "mma.sync.aligned.m16n8k16.row.col.f32.f16.f16.f32 "
                    "{%0,%1,%2,%3}, {%4,%5,%6,%7}, {%8,%9}, {%0,%1,%2,%3};"
                    : "+f"(acc[nt][0]), "+f"(acc[nt][1]), "+f"(acc[nt][2]), "+f"(acc[nt][3])
                    : "r"(a0), "r"(a1), "r"(a2), "r"(a3), "r"(b0), "r"(b1));
            }
        }
    }

    int row = wm * 16 + r0;
    float ps0 = 0.f, ps1 = 0.f, pd0 = 0.f, pd1 = 0.f;
#pragma unroll
    for (int nt = 0; nt < 8; nt++) {
        int colb = wn * 64 + nt * 8 + kq;
        __half2 hlo = __floats2half2_rn(acc[nt][0], acc[nt][1]);
        __half2 hhi = __floats2half2_rn(acc[nt][2], acc[nt][3]);
        *(__half2*)&g_h[(size_t)(nbase + row) * 128 + colb] = hlo;
        *(__half2*)&g_h[(size_t)(nbase + row + 8) * 128 + colb] = hhi;
        float a0v = __ldg(&as[colb]), a1v = __ldg(&as[colb + 1]);
        float d0v = __ldg(&ad[colb]), d1v = __ldg(&ad[colb + 1]);
        ps0 += acc[nt][0] * a0v + acc[nt][1] * a1v;
        ps1 += acc[nt][2] * a0v + acc[nt][3] * a1v;
        pd0 += acc[nt][0] * d0v + acc[nt][1] * d1v;
        pd1 += acc[nt][2] * d0v + acc[nt][3] * d1v;
    }
#pragma unroll
    for (int off = 1; off <= 2; off <<= 1) {
        ps0 += __shfl_xor_sync(0xffffffffu, ps0, off);
        ps1 += __shfl_xor_sync(0xffffffffu, ps1, off);
        pd0 += __shfl_xor_sync(0xffffffffu, pd0, off);
        pd1 += __shfl_xor_sync(0xffffffffu, pd1, off);
    }
    if ((lane & 3) == 0) {
        sEs[row][wn] = ps0; sEs[row + 8][wn] = ps1;
        sEd[row][wn] = pd0; sEd[row + 8][wn] = pd1;
    }
    __syncthreads();
    if (tid < 64) {
        int n = nbase + tid;
        if (n < NN) {
            // pre-scale by log2(e) for the ex2-based softmax in k_agg<2>
            *(float2*)&g_es[2 * n] = make_float2(sEs[tid][0] * L2E, sEs[tid][1] * L2E);
            *(float2*)&g_ed[2 * n] = make_float2(sEd[tid][0] * L2E, sEd[tid][1] * L2E);
        }
    }
}

// ---------------- launch ----------------
extern "C" void kernel_launch(void* const* d_in, const int* in_sizes, int n_in,
                              void* d_out, int out_size) {
    const float* x   = (const float*)d_in[0];
    const int*   ei  = (const int*)d_in[1];
    const float* W1  = (const float*)d_in[2];
    const float* as1 = (const float*)d_in[3];
    const float* ad1 = (const float*)d_in[4];
    const float* b1  = (const float*)d_in[5];
    const float* W2  = (const float*)d_in[6];
    const float* as2 = (const float*)d_in[7];
    const float* ad2 = (const float*)d_in[8];
    const float* b2  = (const float*)d_in[9];
    const float* Wc1 = (const float*)d_in[10];
    const float* bc1 = (const float*)d_in[11];
    const float* Wc2 = (const float*)d_in[12];
    const float* bc2 = (const float*)d_in[13];
    float* out = (float*)d_out;

    k_count_prep<<<CNT_BLKS + 2, 256>>>(ei, W1, as1, ad1, W2);          // 1
    k_scanall<<<SCAN_BLKS, 256>>>();                                    // 2
    k_scatter_transform<<<TR_BLKS + SC_BLKS, 256>>>(ei, x, W1);         // 3
    k_agg<1><<<NN / 32, 256>>>(b1, nullptr, nullptr, nullptr, nullptr, nullptr);   // 4 (profiled)
    k_gemm2<<<NPAD / 64, 256>>>(as2, ad2);                              // 5
    k_agg<2><<<NN / 32, 256>>>(b2, Wc1, bc1, Wc2, bc2, out);            // 6 (fused classifier)
}

// round 15
// speedup vs baseline: 1.1194x; 1.1194x over previous
#include <cuda_runtime.h>
#include <cuda_fp16.h>

#define NN   100000
#define NE   1600000
#define ET   (NE + NN)
#define NPAD 100096   // multiple of 64 for guard-free GEMM tiles
#define SCAN_BLKS ((NN + 1023) / 1024)   // 98
#define CNT4_BLKS ((NE + 1023) / 1024)   // 1563 (4 edges/thread)
#define TR_BLKS   (NN / 16)              // 6250
#define SC4_BLKS  ((NE + 1023) / 1024)   // 1563 (4 edges/thread)
#define SL_BLKS   ((NN + 255) / 256)     // 391 self-loop blocks
#define L2E 1.4426950408889634f

// ---------------- scratch (device globals; no allocations) ----------------
__device__ int    g_deg[NN];          // invariant: all-zero at kernel_launch entry
__device__ int    g_rowptr[NN + 1];
__device__ int    g_rank[NE];         // per-edge rank within its dst segment
__device__ int    g_srcs[ET];
__device__ int    g_aggv[SCAN_BLKS];
__device__ int    g_prefv[SCAN_BLKS];
__device__ int    g_status[SCAN_BLKS];
__device__ float  g_va[7 * 4];        // per-k dot of W1 col-block with a_src/a_dst (xL2E)
__device__ __half g_W2aT[128 * 128];  // fp16 hi part of W2, transposed [N][K]
__device__ __half g_W2bT[128 * 128];  // fp16 residual part, transposed [N][K]
__device__ __half g_h[NPAD * 128];    // transformed features, fp16
__device__ float  g_es[NN * 2];       // attention src scores, PRE-SCALED by log2(e)
__device__ float  g_ed[NN * 2];       // attention dst scores, PRE-SCALED by log2(e)
__device__ __half g_out1[NPAD * 128]; // layer-1 output (relu'd), fp16

__device__ __forceinline__ float ex2f(float x) {
    float r;
    asm("ex2.approx.f32 %0, %1;" : "=f"(r) : "f"(x));
    return r;
}

// ---------------- kernel 1: edge count+rank (x4 vectorized) + prep ----------------
__global__ void k_count_prep(const int* __restrict__ ei,
                             const float* __restrict__ W1,
                             const float* __restrict__ as1, const float* __restrict__ ad1,
                             const float* __restrict__ W2) {
    int b = blockIdx.x;
    int t = threadIdx.x;
    if (b < CNT4_BLKS) {
        int i = (b * 256 + t) * 4;
        if (i + 3 < NE) {
            int4 d4 = *(const int4*)(ei + NE + i);
            int4 r4;
            r4.x = atomicAdd(&g_deg[d4.x], 1);
            r4.y = atomicAdd(&g_deg[d4.y], 1);
            r4.z = atomicAdd(&g_deg[d4.z], 1);
            r4.w = atomicAdd(&g_deg[d4.w], 1);
            *(int4*)(g_rank + i) = r4;
        } else {
            for (int k = 0; k < 4 && i + k < NE; k++)
                g_rank[i + k] = atomicAdd(&g_deg[ei[NE + i + k]], 1);
        }
    } else if (b == CNT4_BLKS) {
        // W2 -> fp16 hi + fp16 residual, transposed to [N][K]
        for (int idx = t; idx < 128 * 128; idx += 256) {
            int k = idx >> 7, n = idx & 127;
            float w = W2[idx];
            __half a = __float2half_rn(w);
            __half bb = __float2half_rn(w - __half2float(a));
            g_W2aT[n * 128 + k] = a;
            g_W2bT[n * 128 + k] = bb;
        }
    } else {
        // va[k][comp]: comp = {es_h0, es_h1, ed_h0, ed_h1}; pre-scaled by log2(e)
        if (t < 28) {
            int k = t >> 2, comp = t & 3;
            int h = comp & 1;
            const float* vec = (comp < 2) ? as1 : ad1;
            float s = 0.f;
#pragma unroll
            for (int c = 0; c < 64; c++) s += W1[k * 128 + h * 64 + c] * vec[h * 64 + c];
            g_va[k * 4 + comp] = s * L2E;
        }
        if (t >= 32 && t < 32 + SCAN_BLKS) g_status[t - 32] = 0;  // reset lookback flags
    }
}

// ---------------- kernel 2: single-pass scan (decoupled lookback) ----------------
__global__ void k_scanall() {  // SCAN_BLKS blocks x 256 threads; 4 nodes/thread
    __shared__ int sh[256];
    __shared__ int s_prefix;
    int b = blockIdx.x;
    int t = threadIdx.x;
    int base = b * 1024;
    int idx = base + t * 4;
    int v[4];
    int s = 0;
#pragma unroll
    for (int r = 0; r < 4; r++) {
        v[r] = (idx + r < NN) ? (g_deg[idx + r] + 1) : 0;  // +1 self-loop
        if (idx + r < NN) g_deg[idx + r] = 0;              // restore invariant
        s += v[r];
    }
    sh[t] = s;
    __syncthreads();
    for (int off = 1; off < 256; off <<= 1) {
        int tv = (t >= off) ? sh[t - off] : 0;
        __syncthreads();
        sh[t] += tv;
        __syncthreads();
    }
    int total = sh[255];
    if (t == 0) {
        if (b == 0) {
            g_prefv[0] = total;
            __threadfence();
            ((volatile int*)g_status)[0] = 2;
            s_prefix = 0;
        } else {
            g_aggv[b] = total;
            __threadfence();
            ((volatile int*)g_status)[b] = 1;
            int run = 0;
            int i = b - 1;
            while (true) {
                int st;
                do { st = ((volatile int*)g_status)[i]; } while (st == 0);
                __threadfence();
                if (st == 1) { run += ((volatile int*)g_aggv)[i]; i--; }
                else         { run += ((volatile int*)g_prefv)[i]; break; }
            }
            g_prefv[b] = run + total;
            __threadfence();
            ((volatile int*)g_status)[b] = 2;
            s_prefix = run;
        }
    }
    __syncthreads();
    int excl = s_prefix + sh[t] - s;
#pragma unroll
    for (int r = 0; r < 4; r++) {
        if (idx + r < NN) {
            g_rowptr[idx + r] = excl;
            excl += v[r];
            if (idx + r == NN - 1) g_rowptr[NN] = excl;
        }
    }
}

// ---------------- kernel 3: fused scatter (atomic-free, x4) + layer-1 transform ----------------
// blocks [0, TR_BLKS): transform; [TR_BLKS, +SC4_BLKS): edge scatter (4/thread);
// [TR_BLKS+SC4_BLKS, +SL_BLKS): self-loop scatter.
__global__ void k_scatter_transform(const int* __restrict__ ei,
                                    const float* __restrict__ x,
                                    const float* __restrict__ W1) {
    int b = blockIdx.x;
    int t = threadIdx.x;
    if (b < TR_BLKS) {
        __shared__ float sx[16 * 7];
        int nb = b * 16;
        int ch = t & 127;
        int hf = t >> 7;
        float w1r[7];
#pragma unroll
        for (int k = 0; k < 7; k++) w1r[k] = __ldg(&W1[k * 128 + ch]);
        if (t < 112) sx[t] = x[nb * 7 + t];
        __syncthreads();
#pragma unroll
        for (int i = 0; i < 8; i++) {
            int j = hf * 8 + i;
            float acc = 0.f;
#pragma unroll
            for (int k = 0; k < 7; k++) acc += sx[j * 7 + k] * w1r[k];
            g_h[(size_t)(nb + j) * 128 + ch] = __float2half(acc);
        }
        // es/ed: 64 threads, 4 components x 16 nodes, 7-FMA dots with g_va (pre-scaled)
        if (t < 64) {
            int j = t >> 2, comp = t & 3;
            int n = nb + j;
            float val = 0.f;
#pragma unroll
            for (int k = 0; k < 7; k++) val += sx[j * 7 + k] * g_va[k * 4 + comp];
            if (comp < 2) g_es[2 * n + comp] = val;
            else          g_ed[2 * n + comp - 2] = val;
        }
    } else if (b < TR_BLKS + SC4_BLKS) {
        int i = ((b - TR_BLKS) * 256 + t) * 4;
        if (i + 3 < NE) {
            int4 s4 = *(const int4*)(ei + i);
            int4 d4 = *(const int4*)(ei + NE + i);
            int4 r4 = *(const int4*)(g_rank + i);
            g_srcs[__ldg(&g_rowptr[d4.x]) + 1 + r4.x] = s4.x;
            g_srcs[__ldg(&g_rowptr[d4.y]) + 1 + r4.y] = s4.y;
            g_srcs[__ldg(&g_rowptr[d4.z]) + 1 + r4.z] = s4.z;
            g_srcs[__ldg(&g_rowptr[d4.w]) + 1 + r4.w] = s4.w;
        } else {
            for (int k = 0; k < 4 && i + k < NE; k++) {
                int s = ei[i + k], d = ei[NE + i + k];
                g_srcs[__ldg(&g_rowptr[d]) + 1 + g_rank[i + k]] = s;
            }
        }
    } else {
        int n = (b - TR_BLKS - SC4_BLKS) * 256 + t;
        if (n < NN) g_srcs[__ldg(&g_rowptr[n])] = n;  // slot 0 = self-loop
    }
}

// ---------------- segment-softmax + aggregation ----------------
// Warp per node (4 sequential). Lane computes (src, w0, w1) for its edge into
// per-warp smem float4; broadcast loop (LDS.128, unroll x4) accumulates both the
// weighted features AND the weight sum redundantly in every lane. Scores are
// pre-scaled by log2(e) so the per-edge weight is a bare ex2.approx.
// LAYER==2 additionally runs the fused classifier for the block's 32 nodes.
template <int LAYER>
__global__ void __launch_bounds__(256, 6) k_agg(const float* __restrict__ bias,
                                                const float* __restrict__ Wc1,
                                                const float* __restrict__ bc1,
                                                const float* __restrict__ Wc2,
                                                const float* __restrict__ bc2,
                                                float* __restrict__ out) {
    __shared__ float4 sMeta[8][32];
    __shared__ float  sCls[LAYER == 2 ? (32 * 64 + 64 * 64 + 64 * 4 + 64 + 4) : 1];
    int wip = threadIdx.x >> 5;
    int gw = (blockIdx.x * blockDim.x + threadIdx.x) >> 5;
    int lane = threadIdx.x & 31;
    int head = lane >> 4;
    float4 bv = make_float4(0.f, 0.f, 0.f, 0.f);
    if (LAYER == 1)      bv = *(const float4*)(bias + lane * 4);
    else if (lane < 16)  bv = *(const float4*)(bias + lane * 4);
    const __half* hlane = g_h + lane * 4;   // lane's 4-channel column base

    for (int q = 0; q < 4; q++) {
        int n = gw * 4 + q;
        int beg = g_rowptr[n], end = g_rowptr[n + 1];
        float2 edv = *(const float2*)(g_ed + 2 * n);

        float sw = 0.f;
        float4 acc = make_float4(0.f, 0.f, 0.f, 0.f);

        for (int base = beg; base < end; base += 32) {
            int j = base + lane;
            float4 meta = make_float4(0.f, 0.f, 0.f, 0.f);
            if (j < end) {
                int src = __ldg(&g_srcs[j]);
                float2 es = *(const float2*)(g_es + 2 * src);
                float e0 = es.x + edv.x; e0 = e0 > 0.f ? e0 : 0.2f * e0;
                float e1 = es.y + edv.y; e1 = e1 > 0.f ? e1 : 0.2f * e1;
                meta = make_float4(__int_as_float(src), ex2f(e0), ex2f(e1), 0.f);
            }
            sMeta[wip][lane] = meta;
            __syncwarp();

            int cnt = end - base; if (cnt > 32) cnt = 32;
            int jj = 0;
            for (; jj + 4 <= cnt; jj += 4) {
                float4 mA = sMeta[wip][jj];
                float4 mB = sMeta[wip][jj + 1];
                float4 mC = sMeta[wip][jj + 2];
                float4 mD = sMeta[wip][jj + 3];
                float wA = head ? mA.z : mA.y;
                float wB = head ? mB.z : mB.y;
                float wC = head ? mC.z : mC.y;
                float wD = head ? mD.z : mD.y;
                uint2 uA = *(const uint2*)(hlane + (size_t)__float_as_int(mA.x) * 128);
                uint2 uB = *(const uint2*)(hlane + (size_t)__float_as_int(mB.x) * 128);
                uint2 uC = *(const uint2*)(hlane + (size_t)__float_as_int(mC.x) * 128);
                uint2 uD = *(const uint2*)(hlane + (size_t)__float_as_int(mD.x) * 128);
                sw += (wA + wB) + (wC + wD);
                float2 a01 = __half22float2(*(__half2*)&uA.x);
                float2 a23 = __half22float2(*(__half2*)&uA.y);
                float2 b01 = __half22float2(*(__half2*)&uB.x);
                float2 b23 = __half22float2(*(__half2*)&uB.y);
                float2 c01 = __half22float2(*(__half2*)&uC.x);
                float2 c23 = __half22float2(*(__half2*)&uC.y);
                float2 d01 = __half22float2(*(__half2*)&uD.x);
                float2 d23 = __half22float2(*(__half2*)&uD.y);
                acc.x += wA * a01.x + wB * b01.x + wC * c01.x + wD * d01.x;
                acc.y += wA * a01.y + wB * b01.y + wC * c01.y + wD * d01.y;
                acc.z += wA * a23.x + wB * b23.x + wC * c23.x + wD * d23.x;
                acc.w += wA * a23.y + wB * b23.y + wC * c23.y + wD * d23.y;
            }
            for (; jj < cnt; jj++) {
                float4 mA = sMeta[wip][jj];
                float wA = head ? mA.z : mA.y;
                uint2 uA = *(const uint2*)(hlane + (size_t)__float_as_int(mA.x) * 128);
                sw += wA;
                float2 a01 = __half22float2(*(__half2*)&uA.x);
                float2 a23 = __half22float2(*(__half2*)&uA.y);
                acc.x += wA * a01.x; acc.y += wA * a01.y;
                acc.z += wA * a23.x; acc.w += wA * a23.y;
            }
            __syncwarp();
        }

        float invs = 1.f / sw;

        if (LAYER == 1) {
            float4 o;
            o.x = fmaxf(acc.x * invs + bv.x, 0.f);
            o.y = fmaxf(acc.y * invs + bv.y, 0.f);
            o.z = fmaxf(acc.z * invs + bv.z, 0.f);
            o.w = fmaxf(acc.w * invs + bv.w, 0.f);
            __half2 h01 = __floats2half2_rn(o.x, o.y);
            __half2 h23 = __floats2half2_rn(o.z, o.w);
            uint2 u;
            u.x = *(unsigned*)&h01; u.y = *(unsigned*)&h23;
            ((uint2*)(g_out1 + (size_t)n * 128))[lane] = u;
        } else {
            acc.x *= invs; acc.y *= invs; acc.z *= invs; acc.w *= invs;
            acc.x += __shfl_xor_sync(0xffffffffu, acc.x, 16);
            acc.y += __shfl_xor_sync(0xffffffffu, acc.y, 16);
            acc.z += __shfl_xor_sync(0xffffffffu, acc.z, 16);
            acc.w += __shfl_xor_sync(0xffffffffu, acc.w, 16);
            if (lane < 16) {
                float4 o;
                o.x = 0.5f * acc.x + bv.x;
                o.y = 0.5f * acc.y + bv.y;
                o.z = 0.5f * acc.z + bv.z;
                o.w = 0.5f * acc.w + bv.w;
                // node-mean output to smem for the fused classifier
                *(float4*)&sCls[(wip * 4 + q) * 64 + lane * 4] = o;
            }
        }
    }

    // ---------------- fused classifier (LAYER==2 only) ----------------
    if (LAYER == 2) {
        float* sOut = sCls;                 // [32][64] node features, then hidden
        float* sW1v = sCls + 2048;          // [64][64]
        float* sW2v = sCls + 2048 + 4096;   // [64][4]
        float* sb1v = sCls + 2048 + 4096 + 256;
        float* sb2v = sCls + 2048 + 4096 + 256 + 64;
        int tid = threadIdx.x;
        int nbase = blockIdx.x * 32;

        __syncthreads();
#pragma unroll
        for (int r = 0; r < 4; r++)
            ((float4*)sW1v)[tid + r * 256] = ((const float4*)Wc1)[tid + r * 256];
        if (tid < 64) {
            ((float4*)sW2v)[tid] = ((const float4*)Wc2)[tid];
            sb1v[tid] = bc1[tid];
        }
        if (tid < 4) sb2v[tid] = bc2[tid];
        __syncthreads();

        // hidden = relu(v @ Wc1 + bc1), 32 nodes in 2 passes, compute to regs
        int node = tid >> 4;
        int cq = tid & 15;
        float hreg[2][4];
#pragma unroll
        for (int p = 0; p < 2; p++) {
            int nd = p * 16 + node;
            float a0 = sb1v[cq * 4], a1 = sb1v[cq * 4 + 1];
            float a2 = sb1v[cq * 4 + 2], a3 = sb1v[cq * 4 + 3];
#pragma unroll
            for (int k = 0; k < 64; k++) {
                float v = sOut[nd * 64 + k];
                float4 wv = *(float4*)&sW1v[k * 64 + cq * 4];
                a0 += v * wv.x; a1 += v * wv.y; a2 += v * wv.z; a3 += v * wv.w;
            }
            hreg[p][0] = fmaxf(a0, 0.f); hreg[p][1] = fmaxf(a1, 0.f);
            hreg[p][2] = fmaxf(a2, 0.f); hreg[p][3] = fmaxf(a3, 0.f);
        }
        __syncthreads();
#pragma unroll
        for (int p = 0; p < 2; p++)
            *(float4*)&sOut[(p * 16 + node) * 64 + cq * 4] =
                make_float4(hreg[p][0], hreg[p][1], hreg[p][2], hreg[p][3]);
        __syncthreads();

        // out = hidden @ Wc2 + bc2 (32 nodes x 4 classes)
        if (tid < 128) {
            int n2 = tid >> 2, o = tid & 3;
            float a = sb2v[o];
#pragma unroll
            for (int k = 0; k < 64; k++) a += sOut[n2 * 64 + k] * sW2v[k * 4 + o];
            out[(size_t)(nbase + n2) * 4 + o] = a;
        }
    }
}

// ---------------- layer 2 GEMM on tensor cores + fused attention scores ----------------
__global__ void k_gemm2(const float* __restrict__ as, const float* __restrict__ ad) {
    __shared__ __half sA[64 * 136];
    __shared__ __half sB[128 * 136];
    __shared__ float  sEs[64][2], sEd[64][2];
    int tid = threadIdx.x;             // 256
    int lane = tid & 31;
    int w = tid >> 5;
    int wm = w >> 1;
    int wn = w & 1;
    int nbase = blockIdx.x * 64;

#pragma unroll
    for (int r = 0; r < 4; r++) {
        int idx = tid + r * 256;
        int row = idx >> 4, c8 = idx & 15;
        uint4 u = ((const uint4*)(g_out1 + (size_t)nbase * 128))[idx];
        *(uint4*)&sA[row * 136 + c8 * 8] = u;
    }

    float acc[8][4];
#pragma unroll
    for (int nt = 0; nt < 8; nt++) { acc[nt][0] = acc[nt][1] = acc[nt][2] = acc[nt][3] = 0.f; }

    int r0 = lane >> 2;
    int kq = (lane & 3) * 2;

    const __half* W2p[2] = {g_W2aT, g_W2bT};
#pragma unroll
    for (int part = 0; part < 2; part++) {
        __syncthreads();
#pragma unroll
        for (int r = 0; r < 8; r++) {
            int idx = tid + r * 256;
            int row = idx >> 4, c8 = idx & 15;
            uint4 u = ((const uint4*)W2p[part])[idx];
            *(uint4*)&sB[row * 136 + c8 * 8] = u;
        }
        __syncthreads();
#pragma unroll
        for (int ks = 0; ks < 8; ks++) {
            int k0 = ks * 16 + kq;
            int arow = wm * 16 + r0;
            unsigned a0 = *(const unsigned*)&sA[arow * 136 + k0];
            unsigned a1 = *(const unsigned*)&sA[(arow + 8) * 136 + k0];
            unsigned a2 = *(const unsigned*)&sA[arow * 136 + k0 + 8];
            unsigned a3 = *(const unsigned*)&sA[(arow + 8) * 136 + k0 + 8];
#pragma unroll
            for (int nt = 0; nt < 8; nt++) {
                int col = wn * 64 + nt * 8 + r0;
                unsigned b0 = *(const unsigned*)&sB[col * 136 + k0];
                unsigned b1 = *(const unsigned*)&sB[col * 136 + k0 + 8];
                asm volatile(
                    "mma.sync.aligned.m16n8k16.row.col.f32.f16.f16.f32 "
                    "{%0,%1,%2,%3}, {%4,%5,%6,%7}, {%8,%9}, {%0,%1,%2,%3};"
                    : "+f"(acc[nt][0]), "+f"(acc[nt][1]), "+f"(acc[nt][2]), "+f"(acc[nt][3])
                    : "r"(a0), "r"(a1), "r"(a2), "r"(a3), "r"(b0), "r"(b1));
            }
        }
    }

    int row = wm * 16 + r0;
    float ps0 = 0.f, ps1 = 0.f, pd0 = 0.f, pd1 = 0.f;
#pragma unroll
    for (int nt = 0; nt < 8; nt++) {
        int colb = wn * 64 + nt * 8 + kq;
        __half2 hlo = __floats2half2_rn(acc[nt][0], acc[nt][1]);
        __half2 hhi = __floats2half2_rn(acc[nt][2], acc[nt][3]);
        *(__half2*)&g_h[(size_t)(nbase + row) * 128 + colb] = hlo;
        *(__half2*)&g_h[(size_t)(nbase + row + 8) * 128 + colb] = hhi;
        float a0v = __ldg(&as[colb]), a1v = __ldg(&as[colb + 1]);
        float d0v = __ldg(&ad[colb]), d1v = __ldg(&ad[colb + 1]);
        ps0 += acc[nt][0] * a0v + acc[nt][1] * a1v;
        ps1 += acc[nt][2] * a0v + acc[nt][3] * a1v;
        pd0 += acc[nt][0] * d0v + acc[nt][1] * d1v;
        pd1 += acc[nt][2] * d0v + acc[nt][3] * d1v;
    }
#pragma unroll
    for (int off = 1; off <= 2; off <<= 1) {
        ps0 += __shfl_xor_sync(0xffffffffu, ps0, off);
        ps1 += __shfl_xor_sync(0xffffffffu, ps1, off);
        pd0 += __shfl_xor_sync(0xffffffffu, pd0, off);
        pd1 += __shfl_xor_sync(0xffffffffu, pd1, off);
    }
    if ((lane & 3) == 0) {
        sEs[row][wn] = ps0; sEs[row + 8][wn] = ps1;
        sEd[row][wn] = pd0; sEd[row + 8][wn] = pd1;
    }
    __syncthreads();
    if (tid < 64) {
        int n = nbase + tid;
        if (n < NN) {
            // pre-scale by log2(e) for the ex2-based softmax in k_agg<2>
            *(float2*)&g_es[2 * n] = make_float2(sEs[tid][0] * L2E, sEs[tid][1] * L2E);
            *(float2*)&g_ed[2 * n] = make_float2(sEd[tid][0] * L2E, sEd[tid][1] * L2E);
        }
    }
}

// ---------------- launch ----------------
extern "C" void kernel_launch(void* const* d_in, const int* in_sizes, int n_in,
                              void* d_out, int out_size) {
    const float* x   = (const float*)d_in[0];
    const int*   ei  = (const int*)d_in[1];
    const float* W1  = (const float*)d_in[2];
    const float* as1 = (const float*)d_in[3];
    const float* ad1 = (const float*)d_in[4];
    const float* b1  = (const float*)d_in[5];
    const float* W2  = (const float*)d_in[6];
    const float* as2 = (const float*)d_in[7];
    const float* ad2 = (const float*)d_in[8];
    const float* b2  = (const float*)d_in[9];
    const float* Wc1 = (const float*)d_in[10];
    const float* bc1 = (const float*)d_in[11];
    const float* Wc2 = (const float*)d_in[12];
    const float* bc2 = (const float*)d_in[13];
    float* out = (float*)d_out;

    k_count_prep<<<CNT4_BLKS + 2, 256>>>(ei, W1, as1, ad1, W2);                 // 1
    k_scanall<<<SCAN_BLKS, 256>>>();                                            // 2
    k_scatter_transform<<<TR_BLKS + SC4_BLKS + SL_BLKS, 256>>>(ei, x, W1);      // 3
    k_agg<1><<<NN / 32, 256>>>(b1, nullptr, nullptr, nullptr, nullptr, nullptr);// 4 (profiled)
    k_gemm2<<<NPAD / 64, 256>>>(as2, ad2);                                      // 5
    k_agg<2><<<NN / 32, 256>>>(b2, Wc1, bc1, Wc2, bc2, out);                    // 6 (fused classifier)
}

// round 16
// speedup vs baseline: 1.1283x; 1.0080x over previous
#include <cuda_runtime.h>
#include <cuda_fp16.h>

#define NN   100000
#define NE   1600000
#define ET   (NE + NN)
#define NPAD 100096   // multiple of 64 for guard-free GEMM tiles
#define SCAN_BLKS ((NN + 1023) / 1024)   // 98
#define CNT4_BLKS ((NE + 1023) / 1024)   // 1563 (4 edges/thread)
#define TR_BLKS   (NN / 16)              // 6250
#define SC4_BLKS  ((NE + 1023) / 1024)   // 1563 (4 edges/thread)
#define SL_BLKS   ((NN + 255) / 256)     // 391 self-loop blocks
#define L2E 1.4426950408889634f

// ---------------- scratch (device globals; no allocations) ----------------
__device__ int    g_deg[NN];          // invariant: all-zero at kernel_launch entry
__device__ int    g_rowptr[NN + 1];
__device__ int    g_rank[NE];         // per-edge rank within its dst segment
__device__ int    g_srcs[ET];
__device__ int    g_aggv[SCAN_BLKS];
__device__ int    g_prefv[SCAN_BLKS];
__device__ int    g_status[SCAN_BLKS];
__device__ __half g_W2aT[128 * 128];  // fp16 hi part of W2, transposed [N][K]
__device__ __half g_W2bT[128 * 128];  // fp16 residual part, transposed [N][K]
__device__ __half g_h[NPAD * 128];    // transformed features, fp16
__device__ float  g_es[NN * 2];       // attention src scores, PRE-SCALED by log2(e)
__device__ float  g_ed[NN * 2];       // attention dst scores, PRE-SCALED by log2(e)
__device__ __half g_out1[NPAD * 128]; // layer-1 output (relu'd), fp16

__device__ __forceinline__ float ex2f(float x) {
    float r;
    asm("ex2.approx.f32 %0, %1;" : "=f"(r) : "f"(x));
    return r;
}

// ---------------- kernel 1: count+rank (x4) || layer-1 transform || prep ----------------
// blocks [0, CNT4_BLKS): edge counting (independent of transform)
// block  CNT4_BLKS:      W2 split/transpose + scan-status reset
// blocks [CNT4_BLKS+1, +TR_BLKS): layer-1 transform (va computed inline per block)
__global__ void k_count_transform(const int* __restrict__ ei,
                                  const float* __restrict__ x,
                                  const float* __restrict__ W1,
                                  const float* __restrict__ as1, const float* __restrict__ ad1,
                                  const float* __restrict__ W2) {
    int b = blockIdx.x;
    int t = threadIdx.x;
    if (b < CNT4_BLKS) {
        int i = (b * 256 + t) * 4;
        if (i + 3 < NE) {
            int4 d4 = *(const int4*)(ei + NE + i);
            int4 r4;
            r4.x = atomicAdd(&g_deg[d4.x], 1);
            r4.y = atomicAdd(&g_deg[d4.y], 1);
            r4.z = atomicAdd(&g_deg[d4.z], 1);
            r4.w = atomicAdd(&g_deg[d4.w], 1);
            *(int4*)(g_rank + i) = r4;
        } else {
            for (int k = 0; k < 4 && i + k < NE; k++)
                g_rank[i + k] = atomicAdd(&g_deg[ei[NE + i + k]], 1);
        }
    } else if (b == CNT4_BLKS) {
        // W2 -> fp16 hi + fp16 residual, transposed to [N][K]
        for (int idx = t; idx < 128 * 128; idx += 256) {
            int k = idx >> 7, n = idx & 127;
            float w = W2[idx];
            __half a = __float2half_rn(w);
            __half bb = __float2half_rn(w - __half2float(a));
            g_W2aT[n * 128 + k] = a;
            g_W2bT[n * 128 + k] = bb;
        }
        if (t >= 32 && t < 32 + SCAN_BLKS) g_status[t - 32] = 0;  // reset lookback flags
    } else {
        // ---- layer-1 transform (16 nodes per block) ----
        __shared__ float sx[16 * 7];
        __shared__ float sva[7 * 4];   // va computed inline (no cross-block ordering needed)
        int nb = (b - CNT4_BLKS - 1) * 16;
        int ch = t & 127;
        int hf = t >> 7;
        // va[k][comp]: comp = {es_h0, es_h1, ed_h0, ed_h1}; pre-scaled by log2(e)
        if (t < 28) {
            int k = t >> 2, comp = t & 3;
            int h = comp & 1;
            const float* vec = (comp < 2) ? as1 : ad1;
            float s = 0.f;
#pragma unroll
            for (int c = 0; c < 64; c++) s += W1[k * 128 + h * 64 + c] * vec[h * 64 + c];
            sva[t] = s * L2E;
        }
        float w1r[7];
#pragma unroll
        for (int k = 0; k < 7; k++) w1r[k] = __ldg(&W1[k * 128 + ch]);
        if (t >= 128 && t < 240) sx[t - 128] = x[nb * 7 + (t - 128)];
        __syncthreads();
#pragma unroll
        for (int i = 0; i < 8; i++) {
            int j = hf * 8 + i;
            float acc = 0.f;
#pragma unroll
            for (int k = 0; k < 7; k++) acc += sx[j * 7 + k] * w1r[k];
            g_h[(size_t)(nb + j) * 128 + ch] = __float2half(acc);
        }
        // es/ed: 64 threads, 4 components x 16 nodes, 7-FMA dots with sva
        if (t < 64) {
            int j = t >> 2, comp = t & 3;
            int n = nb + j;
            float val = 0.f;
#pragma unroll
            for (int k = 0; k < 7; k++) val += sx[j * 7 + k] * sva[k * 4 + comp];
            if (comp < 2) g_es[2 * n + comp] = val;
            else          g_ed[2 * n + comp - 2] = val;
        }
    }
}

// ---------------- kernel 2: single-pass scan (decoupled lookback) ----------------
__global__ void k_scanall() {  // SCAN_BLKS blocks x 256 threads; 4 nodes/thread
    __shared__ int sh[256];
    __shared__ int s_prefix;
    int b = blockIdx.x;
    int t = threadIdx.x;
    int base = b * 1024;
    int idx = base + t * 4;
    int v[4];
    int s = 0;
#pragma unroll
    for (int r = 0; r < 4; r++) {
        v[r] = (idx + r < NN) ? (g_deg[idx + r] + 1) : 0;  // +1 self-loop
        if (idx + r < NN) g_deg[idx + r] = 0;              // restore invariant
        s += v[r];
    }
    sh[t] = s;
    __syncthreads();
    for (int off = 1; off < 256; off <<= 1) {
        int tv = (t >= off) ? sh[t - off] : 0;
        __syncthreads();
        sh[t] += tv;
        __syncthreads();
    }
    int total = sh[255];
    if (t == 0) {
        if (b == 0) {
            g_prefv[0] = total;
            __threadfence();
            ((volatile int*)g_status)[0] = 2;
            s_prefix = 0;
        } else {
            g_aggv[b] = total;
            __threadfence();
            ((volatile int*)g_status)[b] = 1;
            int run = 0;
            int i = b - 1;
            while (true) {
                int st;
                do { st = ((volatile int*)g_status)[i]; } while (st == 0);
                __threadfence();
                if (st == 1) { run += ((volatile int*)g_aggv)[i]; i--; }
                else         { run += ((volatile int*)g_prefv)[i]; break; }
            }
            g_prefv[b] = run + total;
            __threadfence();
            ((volatile int*)g_status)[b] = 2;
            s_prefix = run;
        }
    }
    __syncthreads();
    int excl = s_prefix + sh[t] - s;
#pragma unroll
    for (int r = 0; r < 4; r++) {
        if (idx + r < NN) {
            g_rowptr[idx + r] = excl;
            excl += v[r];
            if (idx + r == NN - 1) g_rowptr[NN] = excl;
        }
    }
}

// ---------------- kernel 3: scatter only (atomic-free, x4) ----------------
__global__ void k_scatter(const int* __restrict__ ei) {
    int b = blockIdx.x;
    int t = threadIdx.x;
    if (b < SC4_BLKS) {
        int i = (b * 256 + t) * 4;
        if (i + 3 < NE) {
            int4 s4 = *(const int4*)(ei + i);
            int4 d4 = *(const int4*)(ei + NE + i);
            int4 r4 = *(const int4*)(g_rank + i);
            g_srcs[__ldg(&g_rowptr[d4.x]) + 1 + r4.x] = s4.x;
            g_srcs[__ldg(&g_rowptr[d4.y]) + 1 + r4.y] = s4.y;
            g_srcs[__ldg(&g_rowptr[d4.z]) + 1 + r4.z] = s4.z;
            g_srcs[__ldg(&g_rowptr[d4.w]) + 1 + r4.w] = s4.w;
        } else {
            for (int k = 0; k < 4 && i + k < NE; k++) {
                int s = ei[i + k], d = ei[NE + i + k];
                g_srcs[__ldg(&g_rowptr[d]) + 1 + g_rank[i + k]] = s;
            }
        }
    } else {
        int n = (b - SC4_BLKS) * 256 + t;
        if (n < NN) g_srcs[__ldg(&g_rowptr[n])] = n;  // slot 0 = self-loop
    }
}

// ---------------- segment-softmax + aggregation ----------------
// Warp per node (4 sequential). Lane computes (src, w0, w1) for its edge into
// per-warp smem float4; broadcast loop (LDS.128, unroll x4) accumulates both the
// weighted features AND the weight sum redundantly in every lane. Scores are
// pre-scaled by log2(e) so the per-edge weight is a bare ex2.approx.
// LAYER==2 additionally runs the fused classifier for the block's 32 nodes.
template <int LAYER>
__global__ void __launch_bounds__(256, 6) k_agg(const float* __restrict__ bias,
                                                const float* __restrict__ Wc1,
                                                const float* __restrict__ bc1,
                                                const float* __restrict__ Wc2,
                                                const float* __restrict__ bc2,
                                                float* __restrict__ out) {
    __shared__ float4 sMeta[8][32];
    __shared__ float  sCls[LAYER == 2 ? (32 * 64 + 64 * 64 + 64 * 4 + 64 + 4) : 1];
    int wip = threadIdx.x >> 5;
    int gw = (blockIdx.x * blockDim.x + threadIdx.x) >> 5;
    int lane = threadIdx.x & 31;
    int head = lane >> 4;
    float4 bv = make_float4(0.f, 0.f, 0.f, 0.f);
    if (LAYER == 1)      bv = *(const float4*)(bias + lane * 4);
    else if (lane < 16)  bv = *(const float4*)(bias + lane * 4);
    const __half* hlane = g_h + lane * 4;   // lane's 4-channel column base

    for (int q = 0; q < 4; q++) {
        int n = gw * 4 + q;
        int beg = g_rowptr[n], end = g_rowptr[n + 1];
        float2 edv = *(const float2*)(g_ed + 2 * n);

        float sw = 0.f;
        float4 acc = make_float4(0.f, 0.f, 0.f, 0.f);

        for (int base = beg; base < end; base += 32) {
            int j = base + lane;
            float4 meta = make_float4(0.f, 0.f, 0.f, 0.f);
            if (j < end) {
                int src = __ldg(&g_srcs[j]);
                float2 es = *(const float2*)(g_es + 2 * src);
                float e0 = es.x + edv.x; e0 = e0 > 0.f ? e0 : 0.2f * e0;
                float e1 = es.y + edv.y; e1 = e1 > 0.f ? e1 : 0.2f * e1;
                meta = make_float4(__int_as_float(src), ex2f(e0), ex2f(e1), 0.f);
            }
            sMeta[wip][lane] = meta;
            __syncwarp();

            int cnt = end - base; if (cnt > 32) cnt = 32;
            int jj = 0;
            for (; jj + 4 <= cnt; jj += 4) {
                float4 mA = sMeta[wip][jj];
                float4 mB = sMeta[wip][jj + 1];
                float4 mC = sMeta[wip][jj + 2];
                float4 mD = sMeta[wip][jj + 3];
                float wA = head ? mA.z : mA.y;
                float wB = head ? mB.z : mB.y;
                float wC = head ? mC.z : mC.y;
                float wD = head ? mD.z : mD.y;
                uint2 uA = *(const uint2*)(hlane + (size_t)__float_as_int(mA.x) * 128);
                uint2 uB = *(const uint2*)(hlane + (size_t)__float_as_int(mB.x) * 128);
                uint2 uC = *(const uint2*)(hlane + (size_t)__float_as_int(mC.x) * 128);
                uint2 uD = *(const uint2*)(hlane + (size_t)__float_as_int(mD.x) * 128);
                sw += (wA + wB) + (wC + wD);
                float2 a01 = __half22float2(*(__half2*)&uA.x);
                float2 a23 = __half22float2(*(__half2*)&uA.y);
                float2 b01 = __half22float2(*(__half2*)&uB.x);
                float2 b23 = __half22float2(*(__half2*)&uB.y);
                float2 c01 = __half22float2(*(__half2*)&uC.x);
                float2 c23 = __half22float2(*(__half2*)&uC.y);
                float2 d01 = __half22float2(*(__half2*)&uD.x);
                float2 d23 = __half22float2(*(__half2*)&uD.y);
                acc.x += wA * a01.x + wB * b01.x + wC * c01.x + wD * d01.x;
                acc.y += wA * a01.y + wB * b01.y + wC * c01.y + wD * d01.y;
                acc.z += wA * a23.x + wB * b23.x + wC * c23.x + wD * d23.x;
                acc.w += wA * a23.y + wB * b23.y + wC * c23.y + wD * d23.y;
            }
            for (; jj < cnt; jj++) {
                float4 mA = sMeta[wip][jj];
                float wA = head ? mA.z : mA.y;
                uint2 uA = *(const uint2*)(hlane + (size_t)__float_as_int(mA.x) * 128);
                sw += wA;
                float2 a01 = __half22float2(*(__half2*)&uA.x);
                float2 a23 = __half22float2(*(__half2*)&uA.y);
                acc.x += wA * a01.x; acc.y += wA * a01.y;
                acc.z += wA * a23.x; acc.w += wA * a23.y;
            }
            __syncwarp();
        }

        float invs = 1.f / sw;

        if (LAYER == 1) {
            float4 o;
            o.x = fmaxf(acc.x * invs + bv.x, 0.f);
            o.y = fmaxf(acc.y * invs + bv.y, 0.f);
            o.z = fmaxf(acc.z * invs + bv.z, 0.f);
            o.w = fmaxf(acc.w * invs + bv.w, 0.f);
            __half2 h01 = __floats2half2_rn(o.x, o.y);
            __half2 h23 = __floats2half2_rn(o.z, o.w);
            uint2 u;
            u.x = *(unsigned*)&h01; u.y = *(unsigned*)&h23;
            ((uint2*)(g_out1 + (size_t)n * 128))[lane] = u;
        } else {
            acc.x *= invs; acc.y *= invs; acc.z *= invs; acc.w *= invs;
            acc.x += __shfl_xor_sync(0xffffffffu, acc.x, 16);
            acc.y += __shfl_xor_sync(0xffffffffu, acc.y, 16);
            acc.z += __shfl_xor_sync(0xffffffffu, acc.z, 16);
            acc.w += __shfl_xor_sync(0xffffffffu, acc.w, 16);
            if (lane < 16) {
                float4 o;
                o.x = 0.5f * acc.x + bv.x;
                o.y = 0.5f * acc.y + bv.y;
                o.z = 0.5f * acc.z + bv.z;
                o.w = 0.5f * acc.w + bv.w;
                // node-mean output to smem for the fused classifier
                *(float4*)&sCls[(wip * 4 + q) * 64 + lane * 4] = o;
            }
        }
    }

    // ---------------- fused classifier (LAYER==2 only) ----------------
    if (LAYER == 2) {
        float* sOut = sCls;                 // [32][64] node features, then hidden
        float* sW1v = sCls + 2048;          // [64][64]
        float* sW2v = sCls + 2048 + 4096;   // [64][4]
        float* sb1v = sCls + 2048 + 4096 + 256;
        float* sb2v = sCls + 2048 + 4096 + 256 + 64;
        int tid = threadIdx.x;
        int nbase = blockIdx.x * 32;

        __syncthreads();
#pragma unroll
        for (int r = 0; r < 4; r++)
            ((float4*)sW1v)[tid + r * 256] = ((const float4*)Wc1)[tid + r * 256];
        if (tid < 64) {
            ((float4*)sW2v)[tid] = ((const float4*)Wc2)[tid];
            sb1v[tid] = bc1[tid];
        }
        if (tid < 4) sb2v[tid] = bc2[tid];
        __syncthreads();

        // hidden = relu(v @ Wc1 + bc1), 32 nodes in 2 passes, compute to regs
        int node = tid >> 4;
        int cq = tid & 15;
        float hreg[2][4];
#pragma unroll
        for (int p = 0; p < 2; p++) {
            int nd = p * 16 + node;
            float a0 = sb1v[cq * 4], a1 = sb1v[cq * 4 + 1];
            float a2 = sb1v[cq * 4 + 2], a3 = sb1v[cq * 4 + 3];
#pragma unroll
            for (int k = 0; k < 64; k++) {
                float v = sOut[nd * 64 + k];
                float4 wv = *(float4*)&sW1v[k * 64 + cq * 4];
                a0 += v * wv.x; a1 += v * wv.y; a2 += v * wv.z; a3 += v * wv.w;
            }
            hreg[p][0] = fmaxf(a0, 0.f); hreg[p][1] = fmaxf(a1, 0.f);
            hreg[p][2] = fmaxf(a2, 0.f); hreg[p][3] = fmaxf(a3, 0.f);
        }
        __syncthreads();
#pragma unroll
        for (int p = 0; p < 2; p++)
            *(float4*)&sOut[(p * 16 + node) * 64 + cq * 4] =
                make_float4(hreg[p][0], hreg[p][1], hreg[p][2], hreg[p][3]);
        __syncthreads();

        // out = hidden @ Wc2 + bc2 (32 nodes x 4 classes)
        if (tid < 128) {
            int n2 = tid >> 2, o = tid & 3;
            float a = sb2v[o];
#pragma unroll
            for (int k = 0; k < 64; k++) a += sOut[n2 * 64 + k] * sW2v[k * 4 + o];
            out[(size_t)(nbase + n2) * 4 + o] = a;
        }
    }
}

// ---------------- layer 2 GEMM on tensor cores + fused attention scores ----------------
__global__ void k_gemm2(const float* __restrict__ as, const float* __restrict__ ad) {
    __shared__ __half sA[64 * 136];
    __shared__ __half sB[128 * 136];
    __shared__ float  sEs[64][2], sEd[64][2];
    int tid = threadIdx.x;             // 256
    int lane = tid & 31;
    int w = tid >> 5;
    int wm = w >> 1;
    int wn = w & 1;
    int nbase = blockIdx.x * 64;

#pragma unroll
    for (int r = 0; r < 4; r++) {
        int idx = tid + r * 256;
        int row = idx >> 4, c8 = idx & 15;
        uint4 u = ((const uint4*)(g_out1 + (size_t)nbase * 128))[idx];
        *(uint4*)&sA[row * 136 + c8 * 8] = u;
    }

    float acc[8][4];
#pragma unroll
    for (int nt = 0; nt < 8; nt++) { acc[nt][0] = acc[nt][1] = acc[nt][2] = acc[nt][3] = 0.f; }

    int r0 = lane >> 2;
    int kq = (lane & 3) * 2;

    const __half* W2p[2] = {g_W2aT, g_W2bT};
#pragma unroll
    for (int part = 0; part < 2; part++) {
        __syncthreads();
#pragma unroll
        for (int r = 0; r < 8; r++) {
            int idx = tid + r * 256;
            int row = idx >> 4, c8 = idx & 15;
            uint4 u = ((const uint4*)W2p[part])[idx];
            *(uint4*)&sB[row * 136 + c8 * 8] = u;
        }
        __syncthreads();
#pragma unroll
        for (int ks = 0; ks < 8; ks++) {
            int k0 = ks * 16 + kq;
            int arow = wm * 16 + r0;
            unsigned a0 = *(const unsigned*)&sA[arow * 136 + k0];
            unsigned a1 = *(const unsigned*)&sA[(arow + 8) * 136 + k0];
            unsigned a2 = *(const unsigned*)&sA[arow * 136 + k0 + 8];
            unsigned a3 = *(const unsigned*)&sA[(arow + 8) * 136 + k0 + 8];
#pragma unroll
            for (int nt = 0; nt < 8; nt++) {
                int col = wn * 64 + nt * 8 + r0;
                unsigned b0 = *(const unsigned*)&sB[col * 136 + k0];
                unsigned b1 = *(const unsigned*)&sB[col * 136 + k0 + 8];
                asm volatile(
                    "mma.sync.aligned.m16n8k16.row.col.f32.f16.f16.f32 "
                    "{%0,%1,%2,%3}, {%4,%5,%6,%7}, {%8,%9}, {%0,%1,%2,%3};"
                    : "+f"(acc[nt][0]), "+f"(acc[nt][1]), "+f"(acc[nt][2]), "+f"(acc[nt][3])
                    : "r"(a0), "r"(a1), "r"(a2), "r"(a3), "r"(b0), "r"(b1));
            }
        }
    }

    int row = wm * 16 + r0;
    float ps0 = 0.f, ps1 = 0.f, pd0 = 0.f, pd1 = 0.f;
#pragma unroll
    for (int nt = 0; nt < 8; nt++) {
        int colb = wn * 64 + nt * 8 + kq;
        __half2 hlo = __floats2half2_rn(acc[nt][0], acc[nt][1]);
        __half2 hhi = __floats2half2_rn(acc[nt][2], acc[nt][3]);
        *(__half2*)&g_h[(size_t)(nbase + row) * 128 + colb] = hlo;
        *(__half2*)&g_h[(size_t)(nbase + row + 8) * 128 + colb] = hhi;
        float a0v = __ldg(&as[colb]), a1v = __ldg(&as[colb + 1]);
        float d0v = __ldg(&ad[colb]), d1v = __ldg(&ad[colb + 1]);
        ps0 += acc[nt][0] * a0v + acc[nt][1] * a1v;
        ps1 += acc[nt][2] * a0v + acc[nt][3] * a1v;
        pd0 += acc[nt][0] * d0v + acc[nt][1] * d1v;
        pd1 += acc[nt][2] * d0v + acc[nt][3] * d1v;
    }
#pragma unroll
    for (int off = 1; off <= 2; off <<= 1) {
        ps0 += __shfl_xor_sync(0xffffffffu, ps0, off);
        ps1 += __shfl_xor_sync(0xffffffffu, ps1, off);
        pd0 += __shfl_xor_sync(0xffffffffu, pd0, off);
        pd1 += __shfl_xor_sync(0xffffffffu, pd1, off);
    }
    if ((lane & 3) == 0) {
        sEs[row][wn] = ps0; sEs[row + 8][wn] = ps1;
        sEd[row][wn] = pd0; sEd[row + 8][wn] = pd1;
    }
    __syncthreads();
    if (tid < 64) {
        int n = nbase + tid;
        if (n < NN) {
            // pre-scale by log2(e) for the ex2-based softmax in k_agg<2>
            *(float2*)&g_es[2 * n] = make_float2(sEs[tid][0] * L2E, sEs[tid][1] * L2E);
            *(float2*)&g_ed[2 * n] = make_float2(sEd[tid][0] * L2E, sEd[tid][1] * L2E);
        }
    }
}

// ---------------- launch ----------------
extern "C" void kernel_launch(void* const* d_in, const int* in_sizes, int n_in,
                              void* d_out, int out_size) {
    const float* x   = (const float*)d_in[0];
    const int*   ei  = (const int*)d_in[1];
    const float* W1  = (const float*)d_in[2];
    const float* as1 = (const float*)d_in[3];
    const float* ad1 = (const float*)d_in[4];
    const float* b1  = (const float*)d_in[5];
    const float* W2  = (const float*)d_in[6];
    const float* as2 = (const float*)d_in[7];
    const float* ad2 = (const float*)d_in[8];
    const float* b2  = (const float*)d_in[9];
    const float* Wc1 = (const float*)d_in[10];
    const float* bc1 = (const float*)d_in[11];
    const float* Wc2 = (const float*)d_in[12];
    const float* bc2 = (const float*)d_in[13];
    float* out = (float*)d_out;

    k_count_transform<<<CNT4_BLKS + 1 + TR_BLKS, 256>>>(ei, x, W1, as1, ad1, W2); // 1
    k_scanall<<<SCAN_BLKS, 256>>>();                                              // 2
    k_scatter<<<SC4_BLKS + SL_BLKS, 256>>>(ei);                                   // 3
    k_agg<1><<<NN / 32, 256>>>(b1, nullptr, nullptr, nullptr, nullptr, nullptr);  // 4 (profiled)
    k_gemm2<<<NPAD / 64, 256>>>(as2, ad2);                                        // 5
    k_agg<2><<<NN / 32, 256>>>(b2, Wc1, bc1, Wc2, bc2, out);                      // 6 (fused classifier)
}